// round 11
// baseline (speedup 1.0000x reference)
#include <cuda_runtime.h>
#include <cuda_bf16.h>
#include <math.h>

#define NN 20000
#define EE 320000
#define FI 128
#define HDIM 32
#define KORD 32
#define HD2 64

// ---------------- static device scratch ----------------
__device__ int   g_deg[NN];
__device__ float g_dis[NN];
__device__ int   g_rowcnt[NN];
__device__ int   g_rowptr[NN + 1];
__device__ int   g_rowfill[NN];
__device__ int2  g_csr[EE];                 // (src, weight bits)
__device__ __nv_bfloat16 g_Wh[2048 * 128];
__device__ __nv_bfloat16 g_Wl[2048 * 128];
__device__ float g_Y[(size_t)KORD * NN * HD2];
__device__ float g_B[3][NN * HD2];
__device__ float g_xp[NN * HDIM];
__device__ float g_asv[NN];
__device__ float g_adv[NN];
__device__ float g_u[NN];
__device__ float g_v[NN];
__device__ float g_p[HDIM];
__device__ float g_q[HDIM];
__device__ float g_cuv[2];
__device__ unsigned g_bar[40];
__device__ int g_flagY[4];

// ---------------- setup kernels ----------------
__global__ void k_zero() {
    int i = blockIdx.x * blockDim.x + threadIdx.x;
    int stride = gridDim.x * blockDim.x;
    for (int t = i; t < NN; t += stride) { g_deg[t] = 0; g_rowcnt[t] = 0; g_rowfill[t] = 0; }
    for (int t = i; t < NN * HD2; t += stride) { g_B[1][t] = 0.f; g_B[2][t] = 0.f; }
    if (i < 40) g_bar[i] = 0u;
    if (i < 4)  g_flagY[i] = 0;
}

__global__ void k_hist(const int* __restrict__ ei) {
    int e = blockIdx.x * blockDim.x + threadIdx.x;
    if (e >= EE) return;
    atomicAdd(&g_deg[ei[e]], 1);
    atomicAdd(&g_rowcnt[ei[EE + e]], 1);
}

__global__ void k_scan() {
    __shared__ int ssum[1024];
    int t = threadIdx.x;
    const int CH = 20;
    int base = t * CH;
    int s = 0;
    for (int i = 0; i < CH; i++) { int idx = base + i; if (idx < NN) s += g_rowcnt[idx]; }
    ssum[t] = s; __syncthreads();
    for (int off = 1; off < 1024; off <<= 1) {
        int v = (t >= off) ? ssum[t - off] : 0;
        __syncthreads();
        ssum[t] += v;
        __syncthreads();
    }
    int run = (t > 0) ? ssum[t - 1] : 0;
    for (int i = 0; i < CH; i++) {
        int idx = base + i;
        if (idx < NN) { g_rowptr[idx] = run; run += g_rowcnt[idx]; }
    }
    if (t == 1023) g_rowptr[NN] = EE;
    for (int i = 0; i < CH; i++) {
        int idx = base + i;
        if (idx < NN) {
            int d = g_deg[idx];
            g_dis[idx] = (d > 0) ? rsqrtf((float)d) : 0.f;
        }
    }
}

__global__ void k_scatter(const int* __restrict__ ei) {
    int e = blockIdx.x * blockDim.x + threadIdx.x;
    if (e >= EE) return;
    int s = ei[e], d = ei[EE + e];
    int pos = g_rowptr[d] + atomicAdd(&g_rowfill[d], 1);
    g_csr[pos] = make_int2(s, __float_as_int(-g_dis[s] * g_dis[d]));
}

__global__ void k_prep_wbf(const float* __restrict__ Wxz, const float* __restrict__ Wxh,
                           int n_base, int n_count) {
    int idx = blockIdx.x * blockDim.x + threadIdx.x;
    if (idx >= n_count * 128) return;
    int n = n_base + (idx >> 7), f = idx & 127;
    int k = n >> 6, j = n & 63;
    float w = (j < HDIM) ? Wxz[(k * FI + f) * HDIM + j]
                         : Wxh[(k * FI + f) * HDIM + (j - HDIM)];
    __nv_bfloat16 h = __float2bfloat16(w);
    g_Wh[(size_t)n * 128 + f] = h;
    g_Wl[(size_t)n * 128 + f] = __float2bfloat16(w - __bfloat162float(h));
}

__global__ void k_prep_pq(const float* __restrict__ Wemb, const float* __restrict__ bemb,
                          const float* __restrict__ Wcls) {
    int t = threadIdx.x;
    int i = t & 31;
    const float* wc = Wcls + ((t < 32) ? 0 : 128);
    float s = 0.f;
    for (int d = 0; d < 128; d++) s += Wemb[i * 128 + d] * wc[d];
    if (t < 32) g_p[i] = s; else g_q[i] = s;
    if (t < 2) {
        const float* w2 = Wcls + t * 128;
        float c = 0.f;
        for (int d = 0; d < 128; d++) c += bemb[d] * w2[d];
        g_cuv[t] = c;
    }
}

__global__ void k_setflag(int ch) {
    __threadfence();
    g_flagY[ch] = 1;
}

// ---------------- bf16 mma.sync GEMM with ldmatrix (R7-proven) ----------------
__device__ __forceinline__ unsigned smem_u32(const void* p) {
    unsigned a;
    asm("{ .reg .u64 t; cvta.to.shared.u64 t, %1; cvt.u32.u64 %0, t; }" : "=r"(a) : "l"(p));
    return a;
}

__device__ __forceinline__ void ldsm4(unsigned* r, unsigned addr) {
    asm volatile("ldmatrix.sync.aligned.m8n8.x4.shared.b16 {%0,%1,%2,%3}, [%4];"
        : "=r"(r[0]), "=r"(r[1]), "=r"(r[2]), "=r"(r[3]) : "r"(addr));
}

__device__ __forceinline__ void mma16(float* c, const unsigned* a, unsigned b0, unsigned b1) {
    asm volatile("mma.sync.aligned.m16n8k16.row.col.f32.bf16.bf16.f32 "
        "{%0,%1,%2,%3},{%4,%5,%6,%7},{%8,%9},{%0,%1,%2,%3};"
        : "+f"(c[0]), "+f"(c[1]), "+f"(c[2]), "+f"(c[3])
        : "r"(a[0]), "r"(a[1]), "r"(a[2]), "r"(a[3]), "r"(b0), "r"(b1));
}

__device__ __forceinline__ void split8(float4 v0, float4 v1, uint4* hi, uint4* lo) {
    float f[8];
    f[0] = v0.x; f[1] = v0.y; f[2] = v0.z; f[3] = v0.w;
    f[4] = v1.x; f[5] = v1.y; f[6] = v1.z; f[7] = v1.w;
    unsigned h[4], l[4];
#pragma unroll
    for (int i = 0; i < 4; i++) {
        float a = f[2 * i], b = f[2 * i + 1];
        __nv_bfloat16 ha = __float2bfloat16(a), hb = __float2bfloat16(b);
        float ra = a - __bfloat162float(ha), rb = b - __bfloat162float(hb);
        __nv_bfloat16 la = __float2bfloat16(ra), lb = __float2bfloat16(rb);
        h[i] = (unsigned)__bfloat16_as_ushort(ha) | ((unsigned)__bfloat16_as_ushort(hb) << 16);
        l[i] = (unsigned)__bfloat16_as_ushort(la) | ((unsigned)__bfloat16_as_ushort(lb) << 16);
    }
    *hi = make_uint4(h[0], h[1], h[2], h[3]);
    *lo = make_uint4(l[0], l[1], l[2], l[3]);
}

__global__ void __launch_bounds__(256) k_gemm(const float* __restrict__ x, int cb_base) {
    __shared__ __align__(16) unsigned char sAh[16384], sAl[16384];
    __shared__ __align__(16) unsigned char sBh[8192],  sBl[8192];
    unsigned bAh = smem_u32(sAh), bAl = smem_u32(sAl);
    unsigned bBh = smem_u32(sBh), bBl = smem_u32(sBl);

    int tid = threadIdx.x, wid = tid >> 5, lane = tid & 31;
    int n0 = blockIdx.x * 128;
    int cb = cb_base + blockIdx.y;
    int m_w = (wid >> 1) * 32;
    int n_w = (wid & 1) * 32;

    float acc[2][4][4];
#pragma unroll
    for (int a = 0; a < 2; a++)
#pragma unroll
        for (int b = 0; b < 4; b++)
#pragma unroll
            for (int c = 0; c < 4; c++) acc[a][b][c] = 0.f;

    for (int kc = 0; kc < 2; kc++) {
        if (kc) __syncthreads();
        {
            int r = tid >> 1, h = tid & 1;
            int gr = n0 + r;
#pragma unroll
            for (int i = 0; i < 4; i++) {
                float4 v0 = make_float4(0.f, 0.f, 0.f, 0.f), v1 = v0;
                if (gr < NN) {
                    const float4* xr = (const float4*)(x + (size_t)gr * FI + kc * 64 + h * 32);
                    v0 = xr[2 * i];
                    v1 = xr[2 * i + 1];
                }
                uint4 hi, lo;
                split8(v0, v1, &hi, &lo);
                int c = h * 4 + i;
                unsigned off = (unsigned)(r * 128 + ((c ^ (r & 7)) << 4));
                *(uint4*)(sAh + off) = hi;
                *(uint4*)(sAl + off) = lo;
            }
        }
        {
            int nr = tid >> 2, q = tid & 3;
            size_t src = (size_t)(cb * 64 + nr) * 128 + kc * 64;
#pragma unroll
            for (int i = 0; i < 2; i++) {
                int c = q * 2 + i;
                uint4 hv = *(const uint4*)(g_Wh + src + c * 8);
                uint4 lv = *(const uint4*)(g_Wl + src + c * 8);
                unsigned off = (unsigned)(nr * 128 + ((c ^ (nr & 7)) << 4));
                *(uint4*)(sBh + off) = hv;
                *(uint4*)(sBl + off) = lv;
            }
        }
        __syncthreads();

#pragma unroll
        for (int s = 0; s < 4; s++) {
            int c0 = s * 2;
            unsigned ah[2][4], al[2][4], bh[2][4], bl[2][4];
#pragma unroll
            for (int mt = 0; mt < 2; mt++) {
                int rr = m_w + mt * 16 + (lane & 15);
                int c = c0 + (lane >> 4);
                unsigned off = (unsigned)(rr * 128 + ((c ^ (rr & 7)) << 4));
                ldsm4(ah[mt], bAh + off);
                ldsm4(al[mt], bAl + off);
            }
#pragma unroll
            for (int ng = 0; ng < 2; ng++) {
                int nr = n_w + ng * 16 + (lane & 15);
                int c = c0 + (lane >> 4);
                unsigned off = (unsigned)(nr * 128 + ((c ^ (nr & 7)) << 4));
                ldsm4(bh[ng], bBh + off);
                ldsm4(bl[ng], bBl + off);
            }
#pragma unroll
            for (int mt = 0; mt < 2; mt++)
#pragma unroll
                for (int ng = 0; ng < 2; ng++)
#pragma unroll
                    for (int hf = 0; hf < 2; hf++) {
                        float* c = acc[mt][ng * 2 + hf];
                        mma16(c, ah[mt], bh[ng][hf], bh[ng][2 + hf]);
                        mma16(c, al[mt], bh[ng][hf], bh[ng][2 + hf]);
                        mma16(c, ah[mt], bl[ng][hf], bl[ng][2 + hf]);
                    }
        }
    }

#pragma unroll
    for (int mt = 0; mt < 2; mt++)
#pragma unroll
        for (int ng = 0; ng < 2; ng++)
#pragma unroll
            for (int hf = 0; hf < 2; hf++) {
                float* c = acc[mt][ng * 2 + hf];
                int m0 = n0 + m_w + mt * 16 + (lane >> 2);
                int col = n_w + ng * 16 + hf * 8 + (lane & 3) * 2;
                if (m0 < NN)
                    *(float2*)(g_Y + ((size_t)cb * NN + m0) * HD2 + col) = make_float2(c[0], c[1]);
                if (m0 + 8 < NN)
                    *(float2*)(g_Y + ((size_t)cb * NN + m0 + 8) * HD2 + col) = make_float2(c[2], c[3]);
            }
}

// ---------------- persistent chain helpers ----------------
__device__ __forceinline__ void wait_flag(int i, int tid) {
    if (tid == 0) {
        while (((volatile int*)g_flagY)[i] == 0) __nanosleep(200);
        __threadfence();
    }
    __syncthreads();
}

__device__ __forceinline__ void gbar(int p, int tid, int nblk) {
    __syncthreads();
    if (tid == 0) {
        __threadfence();
        unsigned n = atomicAdd(&g_bar[p], 1u);
        if (n + 1u < (unsigned)nblk) {
            while (((volatile unsigned*)g_bar)[p] < (unsigned)nblk) __nanosleep(100);
        }
        __threadfence();
    }
    __syncthreads();
}

// edge gather accumulation for one node row (lane holds cols j, j+1)
__device__ __forceinline__ void gather_row(const float* __restrict__ b1, int rs, int re,
                                           int j, float& ax, float& ay) {
    int e = rs;
    for (; e + 4 <= re; e += 4) {
        int2 c0 = __ldcg(&g_csr[e]);
        int2 c1 = __ldcg(&g_csr[e + 1]);
        int2 c2 = __ldcg(&g_csr[e + 2]);
        int2 c3 = __ldcg(&g_csr[e + 3]);
        float2 v0 = __ldcg((const float2*)(b1 + (size_t)c0.x * HD2 + j));
        float2 v1 = __ldcg((const float2*)(b1 + (size_t)c1.x * HD2 + j));
        float2 v2 = __ldcg((const float2*)(b1 + (size_t)c2.x * HD2 + j));
        float2 v3 = __ldcg((const float2*)(b1 + (size_t)c3.x * HD2 + j));
        float w0 = __int_as_float(c0.y), w1 = __int_as_float(c1.y);
        float w2 = __int_as_float(c2.y), w3 = __int_as_float(c3.y);
        ax = fmaf(w0, v0.x, ax); ay = fmaf(w0, v0.y, ay);
        ax = fmaf(w1, v1.x, ax); ay = fmaf(w1, v1.y, ay);
        ax = fmaf(w2, v2.x, ax); ay = fmaf(w2, v2.y, ay);
        ax = fmaf(w3, v3.x, ax); ay = fmaf(w3, v3.y, ay);
    }
    for (; e < re; e++) {
        int2 c = __ldcg(&g_csr[e]);
        float2 v = __ldcg((const float2*)(b1 + (size_t)c.x * HD2 + j));
        float w = __int_as_float(c.y);
        ax = fmaf(w, v.x, ax); ay = fmaf(w, v.y, ay);
    }
}

// ---------------- persistent chain: 31 steps + final/xp + gat + out ----------------
__global__ void __launch_bounds__(256, 4) k_chain(
    const int* __restrict__ ei,
    const float* __restrict__ bxz, const float* __restrict__ bhz,
    const float* __restrict__ bxh, const float* __restrict__ bhh,
    const float* __restrict__ Wg, const float* __restrict__ asrc,
    const float* __restrict__ adst, const float* __restrict__ bgat,
    const float* __restrict__ bcls, float* __restrict__ out, int nblk)
{
    int tid = threadIdx.x;
    int lane = tid & 31;
    int nwarp = nblk * 8;
    int gw0 = blockIdx.x * 8 + (tid >> 5);
    int j = lane * 2;
    int phase = 0;
    int ibn = 0, ib1 = 1, ib2 = 2;

    // ---- steps k = 31 .. 1 ----
    for (int k = KORD - 1; k >= 1; k--) {
        if (k == 31) wait_flag(0, tid);
        else if (k == 23) wait_flag(1, tid);
        else if (k == 15) wait_flag(2, tid);
        else if (k == 7)  wait_flag(3, tid);
        const float* yk = g_Y + (size_t)k * NN * HD2;
        const float* b1 = g_B[ib1];
        const float* b2 = g_B[ib2];
        float* bn = g_B[ibn];
        for (int gw = gw0; gw < NN; gw += nwarp) {
            int rs = g_rowptr[gw], re = g_rowptr[gw + 1];
            float ax = 0.f, ay = 0.f;
            gather_row(b1, rs, re, j, ax, ay);
            float2 y = *(const float2*)(yk + (size_t)gw * HD2 + j);
            float2 p = *(const float2*)(b2 + (size_t)gw * HD2 + j);
            float2 o;
            o.x = y.x + 2.f * ax - p.x;
            o.y = y.y + 2.f * ay - p.y;
            *(float2*)(bn + (size_t)gw * HD2 + j) = o;
        }
        gbar(phase++, tid, nblk);
        int t = ib2; ib2 = ib1; ib1 = ibn; ibn = t;
    }

    // ---- final step (Y[0] + L b1 - b2) fused with gate + xp + attention scalars ----
    {
        const float* b1 = g_B[ib1];
        const float* b2 = g_B[ib2];
        for (int gw = gw0; gw < NN; gw += nwarp) {
            int rs = g_rowptr[gw], re = g_rowptr[gw + 1];
            float ax = 0.f, ay = 0.f;
            gather_row(b1, rs, re, j, ax, ay);
            float2 y = *(const float2*)(g_Y + (size_t)gw * HD2 + j);
            float2 p = *(const float2*)(b2 + (size_t)gw * HD2 + j);
            float ox = y.x + ax - p.x;
            float oy = y.y + ay - p.y;
            float px = __shfl_xor_sync(0xffffffffu, ox, 16);
            float py = __shfl_xor_sync(0xffffffffu, oy, 16);
            float zx = (lane < 16) ? ox : px;
            float zy = (lane < 16) ? oy : py;
            float hx = (lane < 16) ? px : ox;
            float hy = (lane < 16) ? py : oy;
            int j0 = (lane & 15) * 2;
            float z0 = 1.f / (1.f + __expf(-(zx + bxz[j0] + bhz[j0])));
            float z1 = 1.f / (1.f + __expf(-(zy + bxz[j0 + 1] + bhz[j0 + 1])));
            float t0 = tanhf(hx + bxh[j0] + bhh[j0]);
            float t1 = tanhf(hy + bxh[j0 + 1] + bhh[j0 + 1]);
            float h0 = (1.f - z0) * t0;
            float h1 = (1.f - z1) * t1;
            float s0 = __shfl_sync(0xffffffffu, h0, lane >> 1);
            float s1 = __shfl_sync(0xffffffffu, h1, lane >> 1);
            float hval = (lane & 1) ? s1 : s0;
            float xpv = 0.f;
#pragma unroll
            for (int i = 0; i < 32; i++)
                xpv += __shfl_sync(0xffffffffu, hval, i) * Wg[i * HDIM + lane];
            g_xp[(size_t)gw * HDIM + lane] = xpv;
            float a = xpv * asrc[lane];
            float b = xpv * adst[lane];
#pragma unroll
            for (int off = 16; off; off >>= 1) {
                a += __shfl_xor_sync(0xffffffffu, a, off);
                b += __shfl_xor_sync(0xffffffffu, b, off);
            }
            if (lane == 0) { g_asv[gw] = a; g_adv[gw] = b; }
        }
        gbar(phase++, tid, nblk);
    }

    // ---- GAT aggregation (online softmax) + classifier fold ----
    for (int gw = gw0; gw < NN; gw += nwarp) {
        float advd = g_adv[gw];
        float xpd = g_xp[(size_t)gw * HDIM + lane];
        float es = g_asv[gw] + advd;
        es = es > 0.f ? es : 0.2f * es;
        float m = es, ssum = 1.f, acc = xpd;
        int rs = g_rowptr[gw], re = g_rowptr[gw + 1];
        for (int e = rs; e < re; e++) {
            int s = __ldcg(&g_csr[e]).x;
            float sc = __ldcg(&g_asv[s]) + advd;
            sc = sc > 0.f ? sc : 0.2f * sc;
            float xv = __ldcg(&g_xp[(size_t)s * HDIM + lane]);
            float nm = fmaxf(m, sc);
            float r = __expf(m - nm);
            float w = __expf(sc - nm);
            ssum = ssum * r + w;
            acc = acc * r + w * xv;
            m = nm;
        }
        float h2 = acc / ssum + bgat[lane];
        h2 = fmaxf(h2, 0.f);
        float a = h2 * g_p[lane];
        float b = h2 * g_q[lane];
#pragma unroll
        for (int off = 16; off; off >>= 1) {
            a += __shfl_xor_sync(0xffffffffu, a, off);
            b += __shfl_xor_sync(0xffffffffu, b, off);
        }
        if (lane == 0) { g_u[gw] = a + g_cuv[0]; g_v[gw] = b + g_cuv[1]; }
    }
    gbar(phase++, tid, nblk);

    // ---- edge logits ----
    float bc = bcls[0];
    for (int e = blockIdx.x * 256 + tid; e < EE; e += nblk * 256) {
        out[e] = __ldcg(&g_u[ei[e]]) + __ldcg(&g_v[ei[EE + e]]) + bc;
    }
}

// ---------------- launch ----------------
extern "C" void kernel_launch(void* const* d_in, const int* in_sizes, int n_in,
                              void* d_out, int out_size) {
    const float* x    = (const float*)d_in[0];
    const int*   ei   = (const int*)d_in[1];
    const float* Wxz  = (const float*)d_in[2];
    const float* Wxh  = (const float*)d_in[6];
    const float* bxz  = (const float*)d_in[8];
    const float* bhz  = (const float*)d_in[9];
    const float* bxh  = (const float*)d_in[12];
    const float* bhh  = (const float*)d_in[13];
    const float* Wgat = (const float*)d_in[14];
    const float* asrc = (const float*)d_in[15];
    const float* adst = (const float*)d_in[16];
    const float* bgat = (const float*)d_in[17];
    const float* Wemb = (const float*)d_in[18];
    const float* bemb = (const float*)d_in[19];
    const float* Wcls = (const float*)d_in[20];
    const float* bcls = (const float*)d_in[21];
    float* out = (float*)d_out;

    static cudaStream_t s2 = nullptr;
    static cudaEvent_t ev_fork = nullptr, ev_s2done = nullptr;
    static int nblk = 0;
    if (s2 == nullptr) {
        cudaStreamCreateWithFlags(&s2, cudaStreamNonBlocking);
        cudaEventCreateWithFlags(&ev_fork, cudaEventDisableTiming);
        cudaEventCreateWithFlags(&ev_s2done, cudaEventDisableTiming);
        int smc = 0;
        cudaDeviceGetAttribute(&smc, cudaDevAttrMultiProcessorCount, 0);
        if (smc <= 0) smc = 64;               // conservative fallback
        nblk = smc * 2;                        // 2 blocks/SM guaranteed resident (16K regs/blk)
    }

    const int EB = (EE + 255) / 256;

    // k_zero FIRST (clears flags/barriers), then fork s2
    k_zero<<<256, 256>>>();
    cudaEventRecord(ev_fork, 0);
    cudaStreamWaitEvent(s2, ev_fork, 0);

    // s2: 4 GEMM chunks (R8 schedule), each followed by its ready-flag
    for (int ch = 0; ch < 4; ch++) {
        int base = 24 - ch * 8;                 // 24, 16, 8, 0
        k_prep_wbf<<<(8 * 64 * 128 + 255) / 256, 256, 0, s2>>>(Wxz, Wxh, base * 64, 8 * 64);
        k_gemm<<<dim3(157, 8), 256, 0, s2>>>(x, base);
        k_setflag<<<1, 1, 0, s2>>>(ch);
    }
    cudaEventRecord(ev_s2done, s2);

    // main: CSR build + preps (overlaps chunk 0), then the persistent chain
    k_hist<<<EB, 256>>>(ei);
    k_scan<<<1, 1024>>>();
    k_scatter<<<EB, 256>>>(ei);
    k_prep_pq<<<1, 64>>>(Wemb, bemb, Wcls);
    k_chain<<<nblk, 256>>>(ei, bxz, bhz, bxh, bhh, Wgat, asrc, adst, bgat, bcls, out, nblk);

    // join s2 into the capture (after chain; no added serialization)
    cudaStreamWaitEvent(0, ev_s2done, 0);
}

// round 12
// speedup vs baseline: 1.5830x; 1.5830x over previous
#include <cuda_runtime.h>
#include <cuda_bf16.h>
#include <math.h>

#define NN 20000
#define EE 320000
#define FI 128
#define HDIM 32
#define KORD 32
#define HD2 64

// ---------------- static device scratch ----------------
__device__ int   g_deg[NN];
__device__ float g_dis[NN];
__device__ int   g_rowcnt[NN];
__device__ int   g_rowptr[NN + 1];
__device__ int   g_rowfill[NN];
__device__ int2  g_csr[EE];                  // (src, weight bits)
__device__ __nv_bfloat16 g_Wh[2048 * 128];   // [n][f] K-major, hi part
__device__ __nv_bfloat16 g_Wl[2048 * 128];   // lo residual
__device__ float g_Y[(size_t)KORD * NN * HD2];
__device__ float g_B[3][NN * HD2];
__device__ float g_h[NN * HDIM];
__device__ float g_xp[NN * HDIM];
__device__ float g_asv[NN];
__device__ float g_adv[NN];
__device__ float g_u[NN];
__device__ float g_v[NN];
__device__ float g_p[HDIM];
__device__ float g_q[HDIM];
__device__ float g_cuv[2];

// ---------------- setup kernels ----------------
__global__ void k_zero() {
    int i = blockIdx.x * blockDim.x + threadIdx.x;
    int stride = gridDim.x * blockDim.x;
    for (int t = i; t < NN; t += stride) { g_deg[t] = 0; g_rowcnt[t] = 0; g_rowfill[t] = 0; }
    for (int t = i; t < NN * HD2; t += stride) { g_B[1][t] = 0.f; g_B[2][t] = 0.f; }
}

__global__ void k_hist(const int* __restrict__ ei) {
    int e = blockIdx.x * blockDim.x + threadIdx.x;
    if (e >= EE) return;
    atomicAdd(&g_deg[ei[e]], 1);
    atomicAdd(&g_rowcnt[ei[EE + e]], 1);
}

__global__ void k_scan() {
    __shared__ int ssum[1024];
    int t = threadIdx.x;
    const int CH = 20;
    int base = t * CH;
    int s = 0;
    for (int i = 0; i < CH; i++) { int idx = base + i; if (idx < NN) s += g_rowcnt[idx]; }
    ssum[t] = s; __syncthreads();
    for (int off = 1; off < 1024; off <<= 1) {
        int v = (t >= off) ? ssum[t - off] : 0;
        __syncthreads();
        ssum[t] += v;
        __syncthreads();
    }
    int run = (t > 0) ? ssum[t - 1] : 0;
    for (int i = 0; i < CH; i++) {
        int idx = base + i;
        if (idx < NN) { g_rowptr[idx] = run; run += g_rowcnt[idx]; }
    }
    if (t == 1023) g_rowptr[NN] = EE;
    for (int i = 0; i < CH; i++) {
        int idx = base + i;
        if (idx < NN) {
            int d = g_deg[idx];
            g_dis[idx] = (d > 0) ? rsqrtf((float)d) : 0.f;
        }
    }
}

__global__ void k_scatter(const int* __restrict__ ei) {
    int e = blockIdx.x * blockDim.x + threadIdx.x;
    if (e >= EE) return;
    int s = ei[e], d = ei[EE + e];
    int pos = g_rowptr[d] + atomicAdd(&g_rowfill[d], 1);
    g_csr[pos] = make_int2(s, __float_as_int(-g_dis[s] * g_dis[d]));
}

__global__ void k_prep_wbf(const float* __restrict__ Wxz, const float* __restrict__ Wxh,
                           int n_base, int n_count) {
    int idx = blockIdx.x * blockDim.x + threadIdx.x;
    if (idx >= n_count * 128) return;
    int n = n_base + (idx >> 7), f = idx & 127;
    int k = n >> 6, j = n & 63;
    float w = (j < HDIM) ? Wxz[(k * FI + f) * HDIM + j]
                         : Wxh[(k * FI + f) * HDIM + (j - HDIM)];
    __nv_bfloat16 h = __float2bfloat16(w);
    g_Wh[(size_t)n * 128 + f] = h;
    g_Wl[(size_t)n * 128 + f] = __float2bfloat16(w - __bfloat162float(h));
}

__global__ void k_prep_pq(const float* __restrict__ Wemb, const float* __restrict__ bemb,
                          const float* __restrict__ Wcls) {
    int t = threadIdx.x;
    int i = t & 31;
    const float* wc = Wcls + ((t < 32) ? 0 : 128);
    float s = 0.f;
    for (int d = 0; d < 128; d++) s += Wemb[i * 128 + d] * wc[d];
    if (t < 32) g_p[i] = s; else g_q[i] = s;
    if (t < 2) {
        const float* w2 = Wcls + t * 128;
        float c = 0.f;
        for (int d = 0; d < 128; d++) c += bemb[d] * w2[d];
        g_cuv[t] = c;
    }
}

// ---------------- bf16 mma.sync GEMM with ldmatrix (R7-proven) ----------------
__device__ __forceinline__ unsigned smem_u32(const void* p) {
    unsigned a;
    asm("{ .reg .u64 t; cvta.to.shared.u64 t, %1; cvt.u32.u64 %0, t; }" : "=r"(a) : "l"(p));
    return a;
}

__device__ __forceinline__ void ldsm4(unsigned* r, unsigned addr) {
    asm volatile("ldmatrix.sync.aligned.m8n8.x4.shared.b16 {%0,%1,%2,%3}, [%4];"
        : "=r"(r[0]), "=r"(r[1]), "=r"(r[2]), "=r"(r[3]) : "r"(addr));
}

__device__ __forceinline__ void mma16(float* c, const unsigned* a, unsigned b0, unsigned b1) {
    asm volatile("mma.sync.aligned.m16n8k16.row.col.f32.bf16.bf16.f32 "
        "{%0,%1,%2,%3},{%4,%5,%6,%7},{%8,%9},{%0,%1,%2,%3};"
        : "+f"(c[0]), "+f"(c[1]), "+f"(c[2]), "+f"(c[3])
        : "r"(a[0]), "r"(a[1]), "r"(a[2]), "r"(a[3]), "r"(b0), "r"(b1));
}

__device__ __forceinline__ void split8(float4 v0, float4 v1, uint4* hi, uint4* lo) {
    float f[8];
    f[0] = v0.x; f[1] = v0.y; f[2] = v0.z; f[3] = v0.w;
    f[4] = v1.x; f[5] = v1.y; f[6] = v1.z; f[7] = v1.w;
    unsigned h[4], l[4];
#pragma unroll
    for (int i = 0; i < 4; i++) {
        float a = f[2 * i], b = f[2 * i + 1];
        __nv_bfloat16 ha = __float2bfloat16(a), hb = __float2bfloat16(b);
        float ra = a - __bfloat162float(ha), rb = b - __bfloat162float(hb);
        __nv_bfloat16 la = __float2bfloat16(ra), lb = __float2bfloat16(rb);
        h[i] = (unsigned)__bfloat16_as_ushort(ha) | ((unsigned)__bfloat16_as_ushort(hb) << 16);
        l[i] = (unsigned)__bfloat16_as_ushort(la) | ((unsigned)__bfloat16_as_ushort(lb) << 16);
    }
    *hi = make_uint4(h[0], h[1], h[2], h[3]);
    *lo = make_uint4(l[0], l[1], l[2], l[3]);
}

// grid (157, 8) per chunk; cb = cb_base + blockIdx.y
__global__ void __launch_bounds__(256) k_gemm(const float* __restrict__ x, int cb_base) {
    __shared__ __align__(16) unsigned char sAh[16384], sAl[16384];
    __shared__ __align__(16) unsigned char sBh[8192],  sBl[8192];
    unsigned bAh = smem_u32(sAh), bAl = smem_u32(sAl);
    unsigned bBh = smem_u32(sBh), bBl = smem_u32(sBl);

    int tid = threadIdx.x, wid = tid >> 5, lane = tid & 31;
    int n0 = blockIdx.x * 128;
    int cb = cb_base + blockIdx.y;
    int m_w = (wid >> 1) * 32;
    int n_w = (wid & 1) * 32;

    float acc[2][4][4];
#pragma unroll
    for (int a = 0; a < 2; a++)
#pragma unroll
        for (int b = 0; b < 4; b++)
#pragma unroll
            for (int c = 0; c < 4; c++) acc[a][b][c] = 0.f;

    for (int kc = 0; kc < 2; kc++) {
        if (kc) __syncthreads();
        {
            int r = tid >> 1, h = tid & 1;
            int gr = n0 + r;
#pragma unroll
            for (int i = 0; i < 4; i++) {
                float4 v0 = make_float4(0.f, 0.f, 0.f, 0.f), v1 = v0;
                if (gr < NN) {
                    const float4* xr = (const float4*)(x + (size_t)gr * FI + kc * 64 + h * 32);
                    v0 = xr[2 * i];
                    v1 = xr[2 * i + 1];
                }
                uint4 hi, lo;
                split8(v0, v1, &hi, &lo);
                int c = h * 4 + i;
                unsigned off = (unsigned)(r * 128 + ((c ^ (r & 7)) << 4));
                *(uint4*)(sAh + off) = hi;
                *(uint4*)(sAl + off) = lo;
            }
        }
        {
            int nr = tid >> 2, q = tid & 3;
            size_t src = (size_t)(cb * 64 + nr) * 128 + kc * 64;
#pragma unroll
            for (int i = 0; i < 2; i++) {
                int c = q * 2 + i;
                uint4 hv = *(const uint4*)(g_Wh + src + c * 8);
                uint4 lv = *(const uint4*)(g_Wl + src + c * 8);
                unsigned off = (unsigned)(nr * 128 + ((c ^ (nr & 7)) << 4));
                *(uint4*)(sBh + off) = hv;
                *(uint4*)(sBl + off) = lv;
            }
        }
        __syncthreads();

#pragma unroll
        for (int s = 0; s < 4; s++) {
            int c0 = s * 2;
            unsigned ah[2][4], al[2][4], bh[2][4], bl[2][4];
#pragma unroll
            for (int mt = 0; mt < 2; mt++) {
                int rr = m_w + mt * 16 + (lane & 15);
                int c = c0 + (lane >> 4);
                unsigned off = (unsigned)(rr * 128 + ((c ^ (rr & 7)) << 4));
                ldsm4(ah[mt], bAh + off);
                ldsm4(al[mt], bAl + off);
            }
#pragma unroll
            for (int ng = 0; ng < 2; ng++) {
                int nr = n_w + ng * 16 + (lane & 15);
                int c = c0 + (lane >> 4);
                unsigned off = (unsigned)(nr * 128 + ((c ^ (nr & 7)) << 4));
                ldsm4(bh[ng], bBh + off);
                ldsm4(bl[ng], bBl + off);
            }
#pragma unroll
            for (int mt = 0; mt < 2; mt++)
#pragma unroll
                for (int ng = 0; ng < 2; ng++)
#pragma unroll
                    for (int hf = 0; hf < 2; hf++) {
                        float* c = acc[mt][ng * 2 + hf];
                        mma16(c, ah[mt], bh[ng][hf], bh[ng][2 + hf]);
                        mma16(c, al[mt], bh[ng][hf], bh[ng][2 + hf]);
                        mma16(c, ah[mt], bl[ng][hf], bl[ng][2 + hf]);
                    }
        }
    }

#pragma unroll
    for (int mt = 0; mt < 2; mt++)
#pragma unroll
        for (int ng = 0; ng < 2; ng++)
#pragma unroll
            for (int hf = 0; hf < 2; hf++) {
                float* c = acc[mt][ng * 2 + hf];
                int m0 = n0 + m_w + mt * 16 + (lane >> 2);
                int col = n_w + ng * 16 + hf * 8 + (lane & 3) * 2;
                if (m0 < NN)
                    *(float2*)(g_Y + ((size_t)cb * NN + m0) * HD2 + col) = make_float2(c[0], c[1]);
                if (m0 + 8 < NN)
                    *(float2*)(g_Y + ((size_t)cb * NN + m0 + 8) * HD2 + col) = make_float2(c[2], c[3]);
            }
}

// ---------------- unrolled edge gather (int2 CSR, MLP=4) ----------------
__device__ __forceinline__ void gather_row(const float* __restrict__ b1, int rs, int re,
                                           int j, float& ax, float& ay) {
    int e = rs;
    for (; e + 4 <= re; e += 4) {
        int2 c0 = g_csr[e];
        int2 c1 = g_csr[e + 1];
        int2 c2 = g_csr[e + 2];
        int2 c3 = g_csr[e + 3];
        float2 v0 = *(const float2*)(b1 + (size_t)c0.x * HD2 + j);
        float2 v1 = *(const float2*)(b1 + (size_t)c1.x * HD2 + j);
        float2 v2 = *(const float2*)(b1 + (size_t)c2.x * HD2 + j);
        float2 v3 = *(const float2*)(b1 + (size_t)c3.x * HD2 + j);
        float w0 = __int_as_float(c0.y), w1 = __int_as_float(c1.y);
        float w2 = __int_as_float(c2.y), w3 = __int_as_float(c3.y);
        ax = fmaf(w0, v0.x, ax); ay = fmaf(w0, v0.y, ay);
        ax = fmaf(w1, v1.x, ax); ay = fmaf(w1, v1.y, ay);
        ax = fmaf(w2, v2.x, ax); ay = fmaf(w2, v2.y, ay);
        ax = fmaf(w3, v3.x, ax); ay = fmaf(w3, v3.y, ay);
    }
    for (; e < re; e++) {
        int2 c = g_csr[e];
        float2 v = *(const float2*)(b1 + (size_t)c.x * HD2 + j);
        float w = __int_as_float(c.y);
        ax = fmaf(w, v.x, ax); ay = fmaf(w, v.y, ay);
    }
}

// ---------------- Clenshaw step ----------------
__global__ void k_cheb_step(int k, int ibn, int ib1, int ib2) {
    int gw = (blockIdx.x * blockDim.x + threadIdx.x) >> 5;
    int lane = threadIdx.x & 31;
    if (gw >= NN) return;
    const float* yk = g_Y + (size_t)k * NN * HD2;
    const float* b1 = g_B[ib1];
    const float* b2 = g_B[ib2];
    float* bn = g_B[ibn];
    int rs = g_rowptr[gw], re = g_rowptr[gw + 1];
    int j = lane * 2;
    float ax = 0.f, ay = 0.f;
    gather_row(b1, rs, re, j, ax, ay);
    float2 y = *(const float2*)(yk + (size_t)gw * HD2 + j);
    float2 p = *(const float2*)(b2 + (size_t)gw * HD2 + j);
    float2 o;
    o.x = y.x + 2.f * ax - p.x;
    o.y = y.y + 2.f * ay - p.y;
    *(float2*)(bn + (size_t)gw * HD2 + j) = o;
}

__global__ void k_cheb_final(int ib1, int ib2,
                             const float* __restrict__ bxz, const float* __restrict__ bhz,
                             const float* __restrict__ bxh, const float* __restrict__ bhh) {
    int gw = (blockIdx.x * blockDim.x + threadIdx.x) >> 5;
    int lane = threadIdx.x & 31;
    if (gw >= NN) return;
    const float* y0 = g_Y;
    const float* b1 = g_B[ib1];
    const float* b2 = g_B[ib2];
    int rs = g_rowptr[gw], re = g_rowptr[gw + 1];
    int j = lane * 2;
    float ax = 0.f, ay = 0.f;
    gather_row(b1, rs, re, j, ax, ay);
    float2 y = *(const float2*)(y0 + (size_t)gw * HD2 + j);
    float2 p = *(const float2*)(b2 + (size_t)gw * HD2 + j);
    float ox = y.x + ax - p.x;
    float oy = y.y + ay - p.y;
    float px = __shfl_xor_sync(0xffffffffu, ox, 16);
    float py = __shfl_xor_sync(0xffffffffu, oy, 16);
    if (lane < 16) {
        int j0 = lane * 2;
        float z0 = 1.f / (1.f + __expf(-(ox + bxz[j0] + bhz[j0])));
        float z1 = 1.f / (1.f + __expf(-(oy + bxz[j0 + 1] + bhz[j0 + 1])));
        float t0 = tanhf(px + bxh[j0] + bhh[j0]);
        float t1 = tanhf(py + bxh[j0 + 1] + bhh[j0 + 1]);
        float2 hh;
        hh.x = (1.f - z0) * t0;
        hh.y = (1.f - z1) * t1;
        *(float2*)(g_h + (size_t)gw * HDIM + j0) = hh;
    }
}

// ---------------- GAT ----------------
__global__ void k_xp(const float* __restrict__ Wg, const float* __restrict__ asrc,
                     const float* __restrict__ adst) {
    int gw = (blockIdx.x * blockDim.x + threadIdx.x) >> 5;
    int lane = threadIdx.x & 31;
    if (gw >= NN) return;
    float hv = g_h[(size_t)gw * HDIM + lane];
    float xpv = 0.f;
#pragma unroll
    for (int i = 0; i < 32; i++)
        xpv += __shfl_sync(0xffffffffu, hv, i) * Wg[i * HDIM + lane];
    g_xp[(size_t)gw * HDIM + lane] = xpv;
    float a = xpv * asrc[lane];
    float b = xpv * adst[lane];
#pragma unroll
    for (int off = 16; off; off >>= 1) {
        a += __shfl_xor_sync(0xffffffffu, a, off);
        b += __shfl_xor_sync(0xffffffffu, b, off);
    }
    if (lane == 0) { g_asv[gw] = a; g_adv[gw] = b; }
}

__global__ void k_gat(const float* __restrict__ bgat) {
    int gw = (blockIdx.x * blockDim.x + threadIdx.x) >> 5;
    int lane = threadIdx.x & 31;
    if (gw >= NN) return;
    float advd = g_adv[gw];
    float xpd = g_xp[(size_t)gw * HDIM + lane];
    float es = g_asv[gw] + advd;
    es = es > 0.f ? es : 0.2f * es;
    float m = es, ssum = 1.f, acc = xpd;
    int rs = g_rowptr[gw], re = g_rowptr[gw + 1];
    for (int e = rs; e < re; e++) {
        int s = g_csr[e].x;
        float sc = g_asv[s] + advd;
        sc = sc > 0.f ? sc : 0.2f * sc;
        float xv = g_xp[(size_t)s * HDIM + lane];
        float nm = fmaxf(m, sc);
        float r = __expf(m - nm);
        float w = __expf(sc - nm);
        ssum = ssum * r + w;
        acc = acc * r + w * xv;
        m = nm;
    }
    float h2 = acc / ssum + bgat[lane];
    h2 = fmaxf(h2, 0.f);
    float a = h2 * g_p[lane];
    float b = h2 * g_q[lane];
#pragma unroll
    for (int off = 16; off; off >>= 1) {
        a += __shfl_xor_sync(0xffffffffu, a, off);
        b += __shfl_xor_sync(0xffffffffu, b, off);
    }
    if (lane == 0) { g_u[gw] = a + g_cuv[0]; g_v[gw] = b + g_cuv[1]; }
}

__global__ void k_out(const int* __restrict__ ei, const float* __restrict__ bcls,
                      float* __restrict__ out) {
    int e = blockIdx.x * blockDim.x + threadIdx.x;
    if (e >= EE) return;
    out[e] = g_u[ei[e]] + g_v[ei[EE + e]] + bcls[0];
}

// ---------------- launch (R8 overlap schedule) ----------------
extern "C" void kernel_launch(void* const* d_in, const int* in_sizes, int n_in,
                              void* d_out, int out_size) {
    const float* x    = (const float*)d_in[0];
    const int*   ei   = (const int*)d_in[1];
    const float* Wxz  = (const float*)d_in[2];
    const float* Wxh  = (const float*)d_in[6];
    const float* bxz  = (const float*)d_in[8];
    const float* bhz  = (const float*)d_in[9];
    const float* bxh  = (const float*)d_in[12];
    const float* bhh  = (const float*)d_in[13];
    const float* Wgat = (const float*)d_in[14];
    const float* asrc = (const float*)d_in[15];
    const float* adst = (const float*)d_in[16];
    const float* bgat = (const float*)d_in[17];
    const float* Wemb = (const float*)d_in[18];
    const float* bemb = (const float*)d_in[19];
    const float* Wcls = (const float*)d_in[20];
    const float* bcls = (const float*)d_in[21];
    float* out = (float*)d_out;

    static cudaStream_t s2 = nullptr;
    static cudaEvent_t ev_fork = nullptr, ev_chunk[4] = {nullptr, nullptr, nullptr, nullptr};
    if (s2 == nullptr) {
        cudaStreamCreateWithFlags(&s2, cudaStreamNonBlocking);
        cudaEventCreateWithFlags(&ev_fork, cudaEventDisableTiming);
        for (int i = 0; i < 4; i++)
            cudaEventCreateWithFlags(&ev_chunk[i], cudaEventDisableTiming);
    }

    const int EB = (EE + 255) / 256;
    const int NB = (NN * 32 + 255) / 256;

    cudaEventRecord(ev_fork, 0);
    cudaStreamWaitEvent(s2, ev_fork, 0);

    // s2: weight prep + GEMM in 4 chunks, descending cb
    for (int ch = 0; ch < 4; ch++) {
        int base = 24 - ch * 8;                 // 24, 16, 8, 0
        k_prep_wbf<<<(8 * 64 * 128 + 255) / 256, 256, 0, s2>>>(Wxz, Wxh, base * 64, 8 * 64);
        k_gemm<<<dim3(157, 8), 256, 0, s2>>>(x, base);
        cudaEventRecord(ev_chunk[ch], s2);
    }

    // main stream: CSR build + small preps (overlaps chunk 0)
    k_zero<<<256, 256>>>();
    k_hist<<<EB, 256>>>(ei);
    k_scan<<<1, 1024>>>();
    k_scatter<<<EB, 256>>>(ei);
    k_prep_pq<<<1, 64>>>(Wemb, bemb, Wcls);

    // step chain, gated per chunk
    int bn = 0, b1 = 1, b2 = 2;
    cudaStreamWaitEvent(0, ev_chunk[0], 0);
    for (int k = KORD - 1; k >= 1; k--) {
        if (k == 23) cudaStreamWaitEvent(0, ev_chunk[1], 0);
        if (k == 15) cudaStreamWaitEvent(0, ev_chunk[2], 0);
        if (k == 7)  cudaStreamWaitEvent(0, ev_chunk[3], 0);
        k_cheb_step<<<NB, 256>>>(k, bn, b1, b2);
        int t = b2; b2 = b1; b1 = bn; bn = t;
    }
    k_cheb_final<<<NB, 256>>>(b1, b2, bxz, bhz, bxh, bhh);
    k_xp<<<NB, 256>>>(Wgat, asrc, adst);
    k_gat<<<NB, 256>>>(bgat);
    k_out<<<EB, 256>>>(ei, bcls, out);
}

// round 13
// speedup vs baseline: 1.7522x; 1.1069x over previous
#include <cuda_runtime.h>
#include <cuda_bf16.h>
#include <math.h>

#define NN 20000
#define EE 320000
#define FI 128
#define HDIM 32
#define KORD 32
#define HD2 64

// ---------------- static device scratch ----------------
__device__ int   g_deg[NN];
__device__ float g_dis[NN];
__device__ int   g_rowcnt[NN];
__device__ int   g_rowptr[NN + 1];
__device__ int   g_rowfill[NN];
__device__ int   g_csr_src[EE];
__device__ float g_csr_w[EE];
__device__ __nv_bfloat16 g_Wh[2048 * 128];   // [n][f] K-major, hi part
__device__ __nv_bfloat16 g_Wl[2048 * 128];   // lo residual
__device__ float g_Y[(size_t)KORD * NN * HD2];
__device__ float g_B[3][NN * HD2];
__device__ float g_xp[NN * HDIM];
__device__ float g_asv[NN];
__device__ float g_adv[NN];
__device__ float g_u[NN];
__device__ float g_v[NN];
__device__ float g_p[HDIM];
__device__ float g_q[HDIM];
__device__ float g_cuv[2];

// ---------------- setup kernels (R1-proven) ----------------
__global__ void k_zero() {
    int i = blockIdx.x * blockDim.x + threadIdx.x;
    int stride = gridDim.x * blockDim.x;
    for (int t = i; t < NN; t += stride) { g_deg[t] = 0; g_rowcnt[t] = 0; g_rowfill[t] = 0; }
    for (int t = i; t < NN * HD2; t += stride) g_B[2][t] = 0.f;   // only buf2 needs zero
}

__global__ void k_hist(const int* __restrict__ ei) {
    int e = blockIdx.x * blockDim.x + threadIdx.x;
    if (e >= EE) return;
    atomicAdd(&g_deg[ei[e]], 1);
    atomicAdd(&g_rowcnt[ei[EE + e]], 1);
}

__global__ void k_scan() {
    __shared__ int ssum[1024];
    int t = threadIdx.x;
    const int CH = 20;
    int base = t * CH;
    int s = 0;
    for (int i = 0; i < CH; i++) { int idx = base + i; if (idx < NN) s += g_rowcnt[idx]; }
    ssum[t] = s; __syncthreads();
    for (int off = 1; off < 1024; off <<= 1) {
        int v = (t >= off) ? ssum[t - off] : 0;
        __syncthreads();
        ssum[t] += v;
        __syncthreads();
    }
    int run = (t > 0) ? ssum[t - 1] : 0;
    for (int i = 0; i < CH; i++) {
        int idx = base + i;
        if (idx < NN) { g_rowptr[idx] = run; run += g_rowcnt[idx]; }
    }
    if (t == 1023) g_rowptr[NN] = EE;
    for (int i = 0; i < CH; i++) {
        int idx = base + i;
        if (idx < NN) {
            int d = g_deg[idx];
            g_dis[idx] = (d > 0) ? rsqrtf((float)d) : 0.f;
        }
    }
}

__global__ void k_scatter(const int* __restrict__ ei) {
    int e = blockIdx.x * blockDim.x + threadIdx.x;
    if (e >= EE) return;
    int s = ei[e], d = ei[EE + e];
    int pos = g_rowptr[d] + atomicAdd(&g_rowfill[d], 1);
    g_csr_src[pos] = s;
    g_csr_w[pos] = -g_dis[s] * g_dis[d];
}

__global__ void k_prep_wbf(const float* __restrict__ Wxz, const float* __restrict__ Wxh,
                           int n_base, int n_count) {
    int idx = blockIdx.x * blockDim.x + threadIdx.x;
    if (idx >= n_count * 128) return;
    int n = n_base + (idx >> 7), f = idx & 127;
    int k = n >> 6, j = n & 63;
    float w = (j < HDIM) ? Wxz[(k * FI + f) * HDIM + j]
                         : Wxh[(k * FI + f) * HDIM + (j - HDIM)];
    __nv_bfloat16 h = __float2bfloat16(w);
    g_Wh[(size_t)n * 128 + f] = h;
    g_Wl[(size_t)n * 128 + f] = __float2bfloat16(w - __bfloat162float(h));
}

__global__ void k_prep_pq(const float* __restrict__ Wemb, const float* __restrict__ bemb,
                          const float* __restrict__ Wcls) {
    int t = threadIdx.x;
    int i = t & 31;
    const float* wc = Wcls + ((t < 32) ? 0 : 128);
    float s = 0.f;
    for (int d = 0; d < 128; d++) s += Wemb[i * 128 + d] * wc[d];
    if (t < 32) g_p[i] = s; else g_q[i] = s;
    if (t < 2) {
        const float* w2 = Wcls + t * 128;
        float c = 0.f;
        for (int d = 0; d < 128; d++) c += bemb[d] * w2[d];
        g_cuv[t] = c;
    }
}

// ---------------- bf16 mma.sync GEMM with ldmatrix (R7-proven) ----------------
__device__ __forceinline__ unsigned smem_u32(const void* p) {
    unsigned a;
    asm("{ .reg .u64 t; cvta.to.shared.u64 t, %1; cvt.u32.u64 %0, t; }" : "=r"(a) : "l"(p));
    return a;
}

__device__ __forceinline__ void ldsm4(unsigned* r, unsigned addr) {
    asm volatile("ldmatrix.sync.aligned.m8n8.x4.shared.b16 {%0,%1,%2,%3}, [%4];"
        : "=r"(r[0]), "=r"(r[1]), "=r"(r[2]), "=r"(r[3]) : "r"(addr));
}

__device__ __forceinline__ void mma16(float* c, const unsigned* a, unsigned b0, unsigned b1) {
    asm volatile("mma.sync.aligned.m16n8k16.row.col.f32.bf16.bf16.f32 "
        "{%0,%1,%2,%3},{%4,%5,%6,%7},{%8,%9},{%0,%1,%2,%3};"
        : "+f"(c[0]), "+f"(c[1]), "+f"(c[2]), "+f"(c[3])
        : "r"(a[0]), "r"(a[1]), "r"(a[2]), "r"(a[3]), "r"(b0), "r"(b1));
}

__device__ __forceinline__ void split8(float4 v0, float4 v1, uint4* hi, uint4* lo) {
    float f[8];
    f[0] = v0.x; f[1] = v0.y; f[2] = v0.z; f[3] = v0.w;
    f[4] = v1.x; f[5] = v1.y; f[6] = v1.z; f[7] = v1.w;
    unsigned h[4], l[4];
#pragma unroll
    for (int i = 0; i < 4; i++) {
        float a = f[2 * i], b = f[2 * i + 1];
        __nv_bfloat16 ha = __float2bfloat16(a), hb = __float2bfloat16(b);
        float ra = a - __bfloat162float(ha), rb = b - __bfloat162float(hb);
        __nv_bfloat16 la = __float2bfloat16(ra), lb = __float2bfloat16(rb);
        h[i] = (unsigned)__bfloat16_as_ushort(ha) | ((unsigned)__bfloat16_as_ushort(hb) << 16);
        l[i] = (unsigned)__bfloat16_as_ushort(la) | ((unsigned)__bfloat16_as_ushort(lb) << 16);
    }
    *hi = make_uint4(h[0], h[1], h[2], h[3]);
    *lo = make_uint4(l[0], l[1], l[2], l[3]);
}

// grid (157, 8) per chunk; cb = cb_base + blockIdx.y
__global__ void __launch_bounds__(256) k_gemm(const float* __restrict__ x, int cb_base) {
    __shared__ __align__(16) unsigned char sAh[16384], sAl[16384];
    __shared__ __align__(16) unsigned char sBh[8192],  sBl[8192];
    unsigned bAh = smem_u32(sAh), bAl = smem_u32(sAl);
    unsigned bBh = smem_u32(sBh), bBl = smem_u32(sBl);

    int tid = threadIdx.x, wid = tid >> 5, lane = tid & 31;
    int n0 = blockIdx.x * 128;
    int cb = cb_base + blockIdx.y;
    int m_w = (wid >> 1) * 32;
    int n_w = (wid & 1) * 32;

    float acc[2][4][4];
#pragma unroll
    for (int a = 0; a < 2; a++)
#pragma unroll
        for (int b = 0; b < 4; b++)
#pragma unroll
            for (int c = 0; c < 4; c++) acc[a][b][c] = 0.f;

    for (int kc = 0; kc < 2; kc++) {
        if (kc) __syncthreads();
        {
            int r = tid >> 1, h = tid & 1;
            int gr = n0 + r;
#pragma unroll
            for (int i = 0; i < 4; i++) {
                float4 v0 = make_float4(0.f, 0.f, 0.f, 0.f), v1 = v0;
                if (gr < NN) {
                    const float4* xr = (const float4*)(x + (size_t)gr * FI + kc * 64 + h * 32);
                    v0 = xr[2 * i];
                    v1 = xr[2 * i + 1];
                }
                uint4 hi, lo;
                split8(v0, v1, &hi, &lo);
                int c = h * 4 + i;
                unsigned off = (unsigned)(r * 128 + ((c ^ (r & 7)) << 4));
                *(uint4*)(sAh + off) = hi;
                *(uint4*)(sAl + off) = lo;
            }
        }
        {
            int nr = tid >> 2, q = tid & 3;
            size_t src = (size_t)(cb * 64 + nr) * 128 + kc * 64;
#pragma unroll
            for (int i = 0; i < 2; i++) {
                int c = q * 2 + i;
                uint4 hv = *(const uint4*)(g_Wh + src + c * 8);
                uint4 lv = *(const uint4*)(g_Wl + src + c * 8);
                unsigned off = (unsigned)(nr * 128 + ((c ^ (nr & 7)) << 4));
                *(uint4*)(sBh + off) = hv;
                *(uint4*)(sBl + off) = lv;
            }
        }
        __syncthreads();

#pragma unroll
        for (int s = 0; s < 4; s++) {
            int c0 = s * 2;
            unsigned ah[2][4], al[2][4], bh[2][4], bl[2][4];
#pragma unroll
            for (int mt = 0; mt < 2; mt++) {
                int rr = m_w + mt * 16 + (lane & 15);
                int c = c0 + (lane >> 4);
                unsigned off = (unsigned)(rr * 128 + ((c ^ (rr & 7)) << 4));
                ldsm4(ah[mt], bAh + off);
                ldsm4(al[mt], bAl + off);
            }
#pragma unroll
            for (int ng = 0; ng < 2; ng++) {
                int nr = n_w + ng * 16 + (lane & 15);
                int c = c0 + (lane >> 4);
                unsigned off = (unsigned)(nr * 128 + ((c ^ (nr & 7)) << 4));
                ldsm4(bh[ng], bBh + off);
                ldsm4(bl[ng], bBl + off);
            }
#pragma unroll
            for (int mt = 0; mt < 2; mt++)
#pragma unroll
                for (int ng = 0; ng < 2; ng++)
#pragma unroll
                    for (int hf = 0; hf < 2; hf++) {
                        float* c = acc[mt][ng * 2 + hf];
                        mma16(c, ah[mt], bh[ng][hf], bh[ng][2 + hf]);
                        mma16(c, al[mt], bh[ng][hf], bh[ng][2 + hf]);
                        mma16(c, ah[mt], bl[ng][hf], bl[ng][2 + hf]);
                    }
        }
    }

#pragma unroll
    for (int mt = 0; mt < 2; mt++)
#pragma unroll
        for (int ng = 0; ng < 2; ng++)
#pragma unroll
            for (int hf = 0; hf < 2; hf++) {
                float* c = acc[mt][ng * 2 + hf];
                int m0 = n0 + m_w + mt * 16 + (lane >> 2);
                int col = n_w + ng * 16 + hf * 8 + (lane & 3) * 2;
                if (m0 < NN)
                    *(float2*)(g_Y + ((size_t)cb * NN + m0) * HD2 + col) = make_float2(c[0], c[1]);
                if (m0 + 8 < NN)
                    *(float2*)(g_Y + ((size_t)cb * NN + m0 + 8) * HD2 + col) = make_float2(c[2], c[3]);
            }
}

// ---------------- Clenshaw step (R8 gather loop, pointer args) ----------------
__global__ void k_cheb_step(int k, float* __restrict__ bn,
                            const float* __restrict__ b1, const float* __restrict__ b2) {
    int gw = (blockIdx.x * blockDim.x + threadIdx.x) >> 5;
    int lane = threadIdx.x & 31;
    if (gw >= NN) return;
    const float* yk = g_Y + (size_t)k * NN * HD2;
    int rs = g_rowptr[gw], re = g_rowptr[gw + 1];
    int j = lane * 2;
    float ax = 0.f, ay = 0.f;
    for (int e = rs; e < re; e++) {
        int s = g_csr_src[e];
        float w = g_csr_w[e];
        float2 v = *(const float2*)(b1 + (size_t)s * HD2 + j);
        ax += w * v.x; ay += w * v.y;
    }
    float2 y = *(const float2*)(yk + (size_t)gw * HD2 + j);
    float2 p = *(const float2*)(b2 + (size_t)gw * HD2 + j);
    float2 o;
    o.x = y.x + 2.f * ax - p.x;
    o.y = y.y + 2.f * ay - p.y;
    *(float2*)(bn + (size_t)gw * HD2 + j) = o;
}

// final step fused with gate + xp + attention scalars (math validated in R11 run)
__global__ void k_cheb_final_xp(const float* __restrict__ b1, const float* __restrict__ b2,
                                const float* __restrict__ bxz, const float* __restrict__ bhz,
                                const float* __restrict__ bxh, const float* __restrict__ bhh,
                                const float* __restrict__ Wg, const float* __restrict__ asrc,
                                const float* __restrict__ adst) {
    int gw = (blockIdx.x * blockDim.x + threadIdx.x) >> 5;
    int lane = threadIdx.x & 31;
    if (gw >= NN) return;
    int rs = g_rowptr[gw], re = g_rowptr[gw + 1];
    int j = lane * 2;
    float ax = 0.f, ay = 0.f;
    for (int e = rs; e < re; e++) {
        int s = g_csr_src[e];
        float w = g_csr_w[e];
        float2 v = *(const float2*)(b1 + (size_t)s * HD2 + j);
        ax += w * v.x; ay += w * v.y;
    }
    float2 y = *(const float2*)(g_Y + (size_t)gw * HD2 + j);
    float2 p = *(const float2*)(b2 + (size_t)gw * HD2 + j);
    float ox = y.x + ax - p.x;
    float oy = y.y + ay - p.y;
    float px = __shfl_xor_sync(0xffffffffu, ox, 16);
    float py = __shfl_xor_sync(0xffffffffu, oy, 16);
    float zx = (lane < 16) ? ox : px;
    float zy = (lane < 16) ? oy : py;
    float hx = (lane < 16) ? px : ox;
    float hy = (lane < 16) ? py : oy;
    int j0 = (lane & 15) * 2;
    float z0 = 1.f / (1.f + __expf(-(zx + bxz[j0] + bhz[j0])));
    float z1 = 1.f / (1.f + __expf(-(zy + bxz[j0 + 1] + bhz[j0 + 1])));
    float t0 = tanhf(hx + bxh[j0] + bhh[j0]);
    float t1 = tanhf(hy + bxh[j0 + 1] + bhh[j0 + 1]);
    float h0 = (1.f - z0) * t0;
    float h1 = (1.f - z1) * t1;
    float s0 = __shfl_sync(0xffffffffu, h0, lane >> 1);
    float s1 = __shfl_sync(0xffffffffu, h1, lane >> 1);
    float hval = (lane & 1) ? s1 : s0;
    float xpv = 0.f;
#pragma unroll
    for (int i = 0; i < 32; i++)
        xpv += __shfl_sync(0xffffffffu, hval, i) * Wg[i * HDIM + lane];
    g_xp[(size_t)gw * HDIM + lane] = xpv;
    float a = xpv * asrc[lane];
    float b = xpv * adst[lane];
#pragma unroll
    for (int off = 16; off; off >>= 1) {
        a += __shfl_xor_sync(0xffffffffu, a, off);
        b += __shfl_xor_sync(0xffffffffu, b, off);
    }
    if (lane == 0) { g_asv[gw] = a; g_adv[gw] = b; }
}

// ---------------- GAT (R8) ----------------
__global__ void k_gat(const float* __restrict__ bgat) {
    int gw = (blockIdx.x * blockDim.x + threadIdx.x) >> 5;
    int lane = threadIdx.x & 31;
    if (gw >= NN) return;
    float advd = g_adv[gw];
    float xpd = g_xp[(size_t)gw * HDIM + lane];
    float es = g_asv[gw] + advd;
    es = es > 0.f ? es : 0.2f * es;
    float m = es, ssum = 1.f, acc = xpd;
    int rs = g_rowptr[gw], re = g_rowptr[gw + 1];
    for (int e = rs; e < re; e++) {
        int s = g_csr_src[e];
        float sc = g_asv[s] + advd;
        sc = sc > 0.f ? sc : 0.2f * sc;
        float xv = g_xp[(size_t)s * HDIM + lane];
        float nm = fmaxf(m, sc);
        float r = __expf(m - nm);
        float w = __expf(sc - nm);
        ssum = ssum * r + w;
        acc = acc * r + w * xv;
        m = nm;
    }
    float h2 = acc / ssum + bgat[lane];
    h2 = fmaxf(h2, 0.f);
    float a = h2 * g_p[lane];
    float b = h2 * g_q[lane];
#pragma unroll
    for (int off = 16; off; off >>= 1) {
        a += __shfl_xor_sync(0xffffffffu, a, off);
        b += __shfl_xor_sync(0xffffffffu, b, off);
    }
    if (lane == 0) { g_u[gw] = a + g_cuv[0]; g_v[gw] = b + g_cuv[1]; }
}

__global__ void k_out(const int* __restrict__ ei, const float* __restrict__ bcls,
                      float* __restrict__ out) {
    int e = blockIdx.x * blockDim.x + threadIdx.x;
    if (e >= EE) return;
    out[e] = g_u[ei[e]] + g_v[ei[EE + e]] + bcls[0];
}

// ---------------- launch (R8 overlap schedule; step 31 eliminated) ----------------
extern "C" void kernel_launch(void* const* d_in, const int* in_sizes, int n_in,
                              void* d_out, int out_size) {
    const float* x    = (const float*)d_in[0];
    const int*   ei   = (const int*)d_in[1];
    const float* Wxz  = (const float*)d_in[2];
    const float* Wxh  = (const float*)d_in[6];
    const float* bxz  = (const float*)d_in[8];
    const float* bhz  = (const float*)d_in[9];
    const float* bxh  = (const float*)d_in[12];
    const float* bhh  = (const float*)d_in[13];
    const float* Wgat = (const float*)d_in[14];
    const float* asrc = (const float*)d_in[15];
    const float* adst = (const float*)d_in[16];
    const float* bgat = (const float*)d_in[17];
    const float* Wemb = (const float*)d_in[18];
    const float* bemb = (const float*)d_in[19];
    const float* Wcls = (const float*)d_in[20];
    const float* bcls = (const float*)d_in[21];
    float* out = (float*)d_out;

    static cudaStream_t s2 = nullptr;
    static cudaEvent_t ev_fork = nullptr, ev_chunk[4] = {nullptr, nullptr, nullptr, nullptr};
    static float* pB = nullptr;
    static float* pY = nullptr;
    if (s2 == nullptr) {
        cudaStreamCreateWithFlags(&s2, cudaStreamNonBlocking);
        cudaEventCreateWithFlags(&ev_fork, cudaEventDisableTiming);
        for (int i = 0; i < 4; i++)
            cudaEventCreateWithFlags(&ev_chunk[i], cudaEventDisableTiming);
        cudaGetSymbolAddress((void**)&pB, g_B);
        cudaGetSymbolAddress((void**)&pY, g_Y);
    }
    const size_t slab = (size_t)NN * HD2;
    float* buf[3] = { pB, pB + slab, pB + 2 * slab };
    float* Y31 = pY + (size_t)31 * slab;

    const int EB = (EE + 255) / 256;
    const int NB = (NN * 32 + 255) / 256;

    cudaEventRecord(ev_fork, 0);
    cudaStreamWaitEvent(s2, ev_fork, 0);

    // s2: weight prep + GEMM in 4 chunks, descending cb
    for (int ch = 0; ch < 4; ch++) {
        int base = 24 - ch * 8;                 // 24, 16, 8, 0
        k_prep_wbf<<<(8 * 64 * 128 + 255) / 256, 256, 0, s2>>>(Wxz, Wxh, base * 64, 8 * 64);
        k_gemm<<<dim3(157, 8), 256, 0, s2>>>(x, base);
        cudaEventRecord(ev_chunk[ch], s2);
    }

    // main stream: CSR build + small preps (overlaps chunk 0)
    k_zero<<<256, 256>>>();
    k_hist<<<EB, 256>>>(ei);
    k_scan<<<1, 1024>>>();
    k_scatter<<<EB, 256>>>(ei);
    k_prep_pq<<<1, 64>>>(Wemb, bemb, Wcls);

    // step chain: b31 = Y[31] (no kernel); steps k = 30 .. 1
    float* b1 = Y31;
    float* b2 = buf[2];       // zeroed by k_zero
    int idx = 0;
    cudaStreamWaitEvent(0, ev_chunk[0], 0);
    for (int k = KORD - 2; k >= 1; k--) {
        if (k == 23) cudaStreamWaitEvent(0, ev_chunk[1], 0);
        if (k == 15) cudaStreamWaitEvent(0, ev_chunk[2], 0);
        if (k == 7)  cudaStreamWaitEvent(0, ev_chunk[3], 0);
        float* bn = buf[idx];
        k_cheb_step<<<NB, 256>>>(k, bn, b1, b2);
        b2 = b1; b1 = bn; idx = (idx + 1) % 3;
    }
    k_cheb_final_xp<<<NB, 256>>>(b1, b2, bxz, bhz, bxh, bhh, Wgat, asrc, adst);
    k_gat<<<NB, 256>>>(bgat);
    k_out<<<EB, 256>>>(ei, bcls, out);
}

// round 15
// speedup vs baseline: 1.7611x; 1.0051x over previous
#include <cuda_runtime.h>
#include <cuda_bf16.h>
#include <math.h>

#define NN 20000
#define EE 320000
#define FI 128
#define HDIM 32
#define KORD 32
#define HD2 64
#define NROWS 20096   // 157 * 128, padded row count for GEMM

// ---------------- static device scratch ----------------
__device__ int   g_deg[NN];
__device__ float g_dis[NN];
__device__ int   g_rowcnt[NN];
__device__ int   g_rowptr[NN + 1];
__device__ int   g_rowfill[NN];
__device__ int2  g_csr[EE];                  // (src, weight bits)
__device__ __nv_bfloat16 g_Wh[2048 * 128];   // weights hi, [n][f] K-major
__device__ __nv_bfloat16 g_Wl[2048 * 128];   // weights lo residual
__device__ __nv_bfloat16 g_Xh[(size_t)NROWS * 128];  // x hi
__device__ __nv_bfloat16 g_Xl[(size_t)NROWS * 128];  // x lo residual
__device__ float g_Y[(size_t)KORD * NN * HD2];
__device__ float g_B[3][NN * HD2];
__device__ float g_xp[NN * HDIM];
__device__ float g_asv[NN];
__device__ float g_adv[NN];
__device__ float g_u[NN];
__device__ float g_v[NN];
__device__ float g_p[HDIM];
__device__ float g_q[HDIM];
__device__ float g_cuv[2];

// ---------------- setup kernels ----------------
__global__ void k_zero() {
    int i = blockIdx.x * blockDim.x + threadIdx.x;
    int stride = gridDim.x * blockDim.x;
    for (int t = i; t < NN; t += stride) { g_deg[t] = 0; g_rowcnt[t] = 0; g_rowfill[t] = 0; }
    for (int t = i; t < NN * HD2; t += stride) g_B[2][t] = 0.f;   // only buf2 needs zero
}

__global__ void k_hist(const int* __restrict__ ei) {
    int e = blockIdx.x * blockDim.x + threadIdx.x;
    if (e >= EE) return;
    atomicAdd(&g_deg[ei[e]], 1);
    atomicAdd(&g_rowcnt[ei[EE + e]], 1);
}

__global__ void k_scan() {
    __shared__ int ssum[1024];
    int t = threadIdx.x;
    const int CH = 20;
    int base = t * CH;
    int s = 0;
    for (int i = 0; i < CH; i++) { int idx = base + i; if (idx < NN) s += g_rowcnt[idx]; }
    ssum[t] = s; __syncthreads();
    for (int off = 1; off < 1024; off <<= 1) {
        int v = (t >= off) ? ssum[t - off] : 0;
        __syncthreads();
        ssum[t] += v;
        __syncthreads();
    }
    int run = (t > 0) ? ssum[t - 1] : 0;
    for (int i = 0; i < CH; i++) {
        int idx = base + i;
        if (idx < NN) { g_rowptr[idx] = run; run += g_rowcnt[idx]; }
    }
    if (t == 1023) g_rowptr[NN] = EE;
    for (int i = 0; i < CH; i++) {
        int idx = base + i;
        if (idx < NN) {
            int d = g_deg[idx];
            g_dis[idx] = (d > 0) ? rsqrtf((float)d) : 0.f;
        }
    }
}

__global__ void k_scatter(const int* __restrict__ ei) {
    int e = blockIdx.x * blockDim.x + threadIdx.x;
    if (e >= EE) return;
    int s = ei[e], d = ei[EE + e];
    int pos = g_rowptr[d] + atomicAdd(&g_rowfill[d], 1);
    g_csr[pos] = make_int2(s, __float_as_int(-g_dis[s] * g_dis[d]));
}

// x -> bf16 hi/lo (rows >= NN zero-padded)
__global__ void k_prep_x(const float* __restrict__ x) {
    int idx = blockIdx.x * blockDim.x + threadIdx.x;
    if (idx >= NROWS * 128) return;
    int n = idx >> 7;
    float w = (n < NN) ? x[idx] : 0.f;
    __nv_bfloat16 h = __float2bfloat16(w);
    g_Xh[idx] = h;
    g_Xl[idx] = __float2bfloat16(w - __bfloat162float(h));
}

__global__ void k_prep_wbf(const float* __restrict__ Wxz, const float* __restrict__ Wxh,
                           int n_base, int n_count) {
    int idx = blockIdx.x * blockDim.x + threadIdx.x;
    if (idx >= n_count * 128) return;
    int n = n_base + (idx >> 7), f = idx & 127;
    int k = n >> 6, j = n & 63;
    float w = (j < HDIM) ? Wxz[(k * FI + f) * HDIM + j]
                         : Wxh[(k * FI + f) * HDIM + (j - HDIM)];
    __nv_bfloat16 h = __float2bfloat16(w);
    g_Wh[(size_t)n * 128 + f] = h;
    g_Wl[(size_t)n * 128 + f] = __float2bfloat16(w - __bfloat162float(h));
}

__global__ void k_prep_pq(const float* __restrict__ Wemb, const float* __restrict__ bemb,
                          const float* __restrict__ Wcls) {
    int t = threadIdx.x;
    int i = t & 31;
    const float* wc = Wcls + ((t < 32) ? 0 : 128);
    float s = 0.f;
    for (int d = 0; d < 128; d++) s += Wemb[i * 128 + d] * wc[d];
    if (t < 32) g_p[i] = s; else g_q[i] = s;
    if (t < 2) {
        const float* w2 = Wcls + t * 128;
        float c = 0.f;
        for (int d = 0; d < 128; d++) c += bemb[d] * w2[d];
        g_cuv[t] = c;
    }
}

// ---------------- bf16 mma.sync GEMM with ldmatrix ----------------
__device__ __forceinline__ unsigned smem_u32(const void* p) {
    unsigned a;
    asm("{ .reg .u64 t; cvta.to.shared.u64 t, %1; cvt.u32.u64 %0, t; }" : "=r"(a) : "l"(p));
    return a;
}

__device__ __forceinline__ void ldsm4(unsigned* r, unsigned addr) {
    asm volatile("ldmatrix.sync.aligned.m8n8.x4.shared.b16 {%0,%1,%2,%3}, [%4];"
        : "=r"(r[0]), "=r"(r[1]), "=r"(r[2]), "=r"(r[3]) : "r"(addr));
}

__device__ __forceinline__ void mma16(float* c, const unsigned* a, unsigned b0, unsigned b1) {
    asm volatile("mma.sync.aligned.m16n8k16.row.col.f32.bf16.bf16.f32 "
        "{%0,%1,%2,%3},{%4,%5,%6,%7},{%8,%9},{%0,%1,%2,%3};"
        : "+f"(c[0]), "+f"(c[1]), "+f"(c[2]), "+f"(c[3])
        : "r"(a[0]), "r"(a[1]), "r"(a[2]), "r"(a[3]), "r"(b0), "r"(b1));
}

// grid (157, 8) per chunk; cb = cb_base + blockIdx.y
__global__ void __launch_bounds__(256) k_gemm(int cb_base) {
    __shared__ __align__(16) unsigned char sAh[16384], sAl[16384];
    __shared__ __align__(16) unsigned char sBh[8192],  sBl[8192];
    unsigned bAh = smem_u32(sAh), bAl = smem_u32(sAl);
    unsigned bBh = smem_u32(sBh), bBl = smem_u32(sBl);

    int tid = threadIdx.x, wid = tid >> 5, lane = tid & 31;
    int n0 = blockIdx.x * 128;
    int cb = cb_base + blockIdx.y;
    int m_w = (wid >> 1) * 32;
    int n_w = (wid & 1) * 32;

    float acc[2][4][4];
#pragma unroll
    for (int a = 0; a < 2; a++)
#pragma unroll
        for (int b = 0; b < 4; b++)
#pragma unroll
            for (int c = 0; c < 4; c++) acc[a][b][c] = 0.f;

    for (int kc = 0; kc < 2; kc++) {
        if (kc) __syncthreads();
        // A tile: direct bf16 loads from g_Xh/g_Xl
        {
            int r = tid >> 1, h = tid & 1;
            const uint4* xh = (const uint4*)(g_Xh + (size_t)(n0 + r) * 128);
            const uint4* xl = (const uint4*)(g_Xl + (size_t)(n0 + r) * 128);
#pragma unroll
            for (int i = 0; i < 4; i++) {
                int qi = kc * 8 + h * 4 + i;
                uint4 hv = xh[qi];
                uint4 lv = xl[qi];
                int c = h * 4 + i;
                unsigned off = (unsigned)(r * 128 + ((c ^ (r & 7)) << 4));
                *(uint4*)(sAh + off) = hv;
                *(uint4*)(sAl + off) = lv;
            }
        }
        // B tile
        {
            int nr = tid >> 2, q = tid & 3;
            size_t src = (size_t)(cb * 64 + nr) * 128 + kc * 64;
#pragma unroll
            for (int i = 0; i < 2; i++) {
                int c = q * 2 + i;
                uint4 hv = *(const uint4*)(g_Wh + src + c * 8);
                uint4 lv = *(const uint4*)(g_Wl + src + c * 8);
                unsigned off = (unsigned)(nr * 128 + ((c ^ (nr & 7)) << 4));
                *(uint4*)(sBh + off) = hv;
                *(uint4*)(sBl + off) = lv;
            }
        }
        __syncthreads();

#pragma unroll
        for (int s = 0; s < 4; s++) {
            int c0 = s * 2;
            unsigned ah[2][4], al[2][4], bh[2][4], bl[2][4];
#pragma unroll
            for (int mt = 0; mt < 2; mt++) {
                int rr = m_w + mt * 16 + (lane & 15);
                int c = c0 + (lane >> 4);
                unsigned off = (unsigned)(rr * 128 + ((c ^ (rr & 7)) << 4));
                ldsm4(ah[mt], bAh + off);
                ldsm4(al[mt], bAl + off);
            }
#pragma unroll
            for (int ng = 0; ng < 2; ng++) {
                int nr = n_w + ng * 16 + (lane & 15);
                int c = c0 + (lane >> 4);
                unsigned off = (unsigned)(nr * 128 + ((c ^ (nr & 7)) << 4));
                ldsm4(bh[ng], bBh + off);
                ldsm4(bl[ng], bBl + off);
            }
#pragma unroll
            for (int mt = 0; mt < 2; mt++)
#pragma unroll
                for (int ng = 0; ng < 2; ng++)
#pragma unroll
                    for (int hf = 0; hf < 2; hf++) {
                        float* c = acc[mt][ng * 2 + hf];
                        mma16(c, ah[mt], bh[ng][hf], bh[ng][2 + hf]);
                        mma16(c, al[mt], bh[ng][hf], bh[ng][2 + hf]);
                        mma16(c, ah[mt], bl[ng][hf], bl[ng][2 + hf]);
                    }
        }
    }

#pragma unroll
    for (int mt = 0; mt < 2; mt++)
#pragma unroll
        for (int ng = 0; ng < 2; ng++)
#pragma unroll
            for (int hf = 0; hf < 2; hf++) {
                float* c = acc[mt][ng * 2 + hf];
                int m0 = n0 + m_w + mt * 16 + (lane >> 2);
                int col = n_w + ng * 16 + hf * 8 + (lane & 3) * 2;
                if (m0 < NN)
                    *(float2*)(g_Y + ((size_t)cb * NN + m0) * HD2 + col) = make_float2(c[0], c[1]);
                if (m0 + 8 < NN)
                    *(float2*)(g_Y + ((size_t)cb * NN + m0 + 8) * HD2 + col) = make_float2(c[2], c[3]);
            }
}

// ---------------- Clenshaw step (R8 gather loop; int2 CSR) ----------------
__global__ void k_cheb_step(int k, float* __restrict__ bn,
                            const float* __restrict__ b1, const float* __restrict__ b2) {
    int gw = (blockIdx.x * blockDim.x + threadIdx.x) >> 5;
    int lane = threadIdx.x & 31;
    if (gw >= NN) return;
    const float* yk = g_Y + (size_t)k * NN * HD2;
    int rs = g_rowptr[gw], re = g_rowptr[gw + 1];
    int j = lane * 2;
    float ax = 0.f, ay = 0.f;
    for (int e = rs; e < re; e++) {
        int2 c = g_csr[e];
        float w = __int_as_float(c.y);
        float2 v = *(const float2*)(b1 + (size_t)c.x * HD2 + j);
        ax += w * v.x; ay += w * v.y;
    }
    float2 y = *(const float2*)(yk + (size_t)gw * HD2 + j);
    float2 p = *(const float2*)(b2 + (size_t)gw * HD2 + j);
    float2 o;
    o.x = y.x + 2.f * ax - p.x;
    o.y = y.y + 2.f * ay - p.y;
    *(float2*)(bn + (size_t)gw * HD2 + j) = o;
}

// final step fused with gate + xp + attention scalars
__global__ void k_cheb_final_xp(const float* __restrict__ b1, const float* __restrict__ b2,
                                const float* __restrict__ bxz, const float* __restrict__ bhz,
                                const float* __restrict__ bxh, const float* __restrict__ bhh,
                                const float* __restrict__ Wg, const float* __restrict__ asrc,
                                const float* __restrict__ adst) {
    int gw = (blockIdx.x * blockDim.x + threadIdx.x) >> 5;
    int lane = threadIdx.x & 31;
    if (gw >= NN) return;
    int rs = g_rowptr[gw], re = g_rowptr[gw + 1];
    int j = lane * 2;
    float ax = 0.f, ay = 0.f;
    for (int e = rs; e < re; e++) {
        int2 c = g_csr[e];
        float w = __int_as_float(c.y);
        float2 v = *(const float2*)(b1 + (size_t)c.x * HD2 + j);
        ax += w * v.x; ay += w * v.y;
    }
    float2 y = *(const float2*)(g_Y + (size_t)gw * HD2 + j);
    float2 p = *(const float2*)(b2 + (size_t)gw * HD2 + j);
    float ox = y.x + ax - p.x;
    float oy = y.y + ay - p.y;
    float px = __shfl_xor_sync(0xffffffffu, ox, 16);
    float py = __shfl_xor_sync(0xffffffffu, oy, 16);
    float zx = (lane < 16) ? ox : px;
    float zy = (lane < 16) ? oy : py;
    float hx = (lane < 16) ? px : ox;
    float hy = (lane < 16) ? py : oy;
    int j0 = (lane & 15) * 2;
    float z0 = 1.f / (1.f + __expf(-(zx + bxz[j0] + bhz[j0])));
    float z1 = 1.f / (1.f + __expf(-(zy + bxz[j0 + 1] + bhz[j0 + 1])));
    float t0 = tanhf(hx + bxh[j0] + bhh[j0]);
    float t1 = tanhf(hy + bxh[j0 + 1] + bhh[j0 + 1]);
    float h0 = (1.f - z0) * t0;
    float h1 = (1.f - z1) * t1;
    float s0 = __shfl_sync(0xffffffffu, h0, lane >> 1);
    float s1 = __shfl_sync(0xffffffffu, h1, lane >> 1);
    float hval = (lane & 1) ? s1 : s0;
    float xpv = 0.f;
#pragma unroll
    for (int i = 0; i < 32; i++)
        xpv += __shfl_sync(0xffffffffu, hval, i) * Wg[i * HDIM + lane];
    g_xp[(size_t)gw * HDIM + lane] = xpv;
    float a = xpv * asrc[lane];
    float b = xpv * adst[lane];
#pragma unroll
    for (int off = 16; off; off >>= 1) {
        a += __shfl_xor_sync(0xffffffffu, a, off);
        b += __shfl_xor_sync(0xffffffffu, b, off);
    }
    if (lane == 0) { g_asv[gw] = a; g_adv[gw] = b; }
}

// ---------------- GAT: two-pass softmax, lane-batched exp ----------------
__global__ void k_gat(const float* __restrict__ bgat) {
    int gw = (blockIdx.x * blockDim.x + threadIdx.x) >> 5;
    int lane = threadIdx.x & 31;
    if (gw >= NN) return;
    float advd = g_adv[gw];
    float xpd = g_xp[(size_t)gw * HDIM + lane];
    float es = g_asv[gw] + advd;                       // self-loop score (same on all lanes)
    es = es > 0.f ? es : 0.2f * es;
    int rs = g_rowptr[gw], re = g_rowptr[gw + 1];

    // pass A: max score (lanes stride edges)
    float m = es;
    for (int idx = rs + lane; idx < re; idx += 32) {
        int s = g_csr[idx].x;
        float sc = g_asv[s] + advd;
        sc = sc > 0.f ? sc : 0.2f * sc;
        m = fmaxf(m, sc);
    }
#pragma unroll
    for (int off = 16; off; off >>= 1)
        m = fmaxf(m, __shfl_xor_sync(0xffffffffu, m, off));

    // pass B: one exp per edge (computed by one lane), broadcast for weighted sum
    float wself = __expf(es - m);
    float acc = wself * xpd;
    float ssum_part = (lane == 0) ? wself : 0.f;
    for (int base = rs; base < re; base += 32) {
        int idx2 = base + lane;
        float wl = 0.f; int sl = 0;
        if (idx2 < re) {
            sl = g_csr[idx2].x;
            float sc = g_asv[sl] + advd;
            sc = sc > 0.f ? sc : 0.2f * sc;
            wl = __expf(sc - m);
        }
        ssum_part += wl;
        int n = min(32, re - base);
        for (int i = 0; i < n; i++) {
            float wi = __shfl_sync(0xffffffffu, wl, i);
            int si = __shfl_sync(0xffffffffu, sl, i);
            acc += wi * g_xp[(size_t)si * HDIM + lane];
        }
    }
    // total sum across lanes
    float ssum = ssum_part;
#pragma unroll
    for (int off = 16; off; off >>= 1)
        ssum += __shfl_xor_sync(0xffffffffu, ssum, off);

    float h2 = acc / ssum + bgat[lane];
    h2 = fmaxf(h2, 0.f);
    float a = h2 * g_p[lane];
    float b = h2 * g_q[lane];
#pragma unroll
    for (int off = 16; off; off >>= 1) {
        a += __shfl_xor_sync(0xffffffffu, a, off);
        b += __shfl_xor_sync(0xffffffffu, b, off);
    }
    if (lane == 0) { g_u[gw] = a + g_cuv[0]; g_v[gw] = b + g_cuv[1]; }
}

__global__ void k_out(const int* __restrict__ ei, const float* __restrict__ bcls,
                      float* __restrict__ out) {
    int e = blockIdx.x * blockDim.x + threadIdx.x;
    if (e >= EE) return;
    out[e] = g_u[ei[e]] + g_v[ei[EE + e]] + bcls[0];
}

// ---------------- launch (R13 schedule + prep_x) ----------------
extern "C" void kernel_launch(void* const* d_in, const int* in_sizes, int n_in,
                              void* d_out, int out_size) {
    const float* x    = (const float*)d_in[0];
    const int*   ei   = (const int*)d_in[1];
    const float* Wxz  = (const float*)d_in[2];
    const float* Wxh  = (const float*)d_in[6];
    const float* bxz  = (const float*)d_in[8];
    const float* bhz  = (const float*)d_in[9];
    const float* bxh  = (const float*)d_in[12];
    const float* bhh  = (const float*)d_in[13];
    const float* Wgat = (const float*)d_in[14];
    const float* asrc = (const float*)d_in[15];
    const float* adst = (const float*)d_in[16];
    const float* bgat = (const float*)d_in[17];
    const float* Wemb = (const float*)d_in[18];
    const float* bemb = (const float*)d_in[19];
    const float* Wcls = (const float*)d_in[20];
    const float* bcls = (const float*)d_in[21];
    float* out = (float*)d_out;

    static cudaStream_t s2 = nullptr;
    static cudaEvent_t ev_fork = nullptr, ev_chunk[4] = {nullptr, nullptr, nullptr, nullptr};
    static float* pB = nullptr;
    static float* pY = nullptr;
    if (s2 == nullptr) {
        cudaStreamCreateWithFlags(&s2, cudaStreamNonBlocking);
        cudaEventCreateWithFlags(&ev_fork, cudaEventDisableTiming);
        for (int i = 0; i < 4; i++)
            cudaEventCreateWithFlags(&ev_chunk[i], cudaEventDisableTiming);
        cudaGetSymbolAddress((void**)&pB, g_B);
        cudaGetSymbolAddress((void**)&pY, g_Y);
    }
    const size_t slab = (size_t)NN * HD2;
    float* buf[3] = { pB, pB + slab, pB + 2 * slab };
    float* Y31 = pY + (size_t)31 * slab;

    const int EB = (EE + 255) / 256;
    const int NB = (NN * 32 + 255) / 256;

    cudaEventRecord(ev_fork, 0);
    cudaStreamWaitEvent(s2, ev_fork, 0);

    // s2: x conversion once, then weight prep + GEMM in 4 chunks, descending cb
    k_prep_x<<<(NROWS * 128 + 255) / 256, 256, 0, s2>>>(x);
    for (int ch = 0; ch < 4; ch++) {
        int base = 24 - ch * 8;                 // 24, 16, 8, 0
        k_prep_wbf<<<(8 * 64 * 128 + 255) / 256, 256, 0, s2>>>(Wxz, Wxh, base * 64, 8 * 64);
        k_gemm<<<dim3(157, 8), 256, 0, s2>>>(base);
        cudaEventRecord(ev_chunk[ch], s2);
    }

    // main stream: CSR build + small preps (overlaps chunk 0)
    k_zero<<<256, 256>>>();
    k_hist<<<EB, 256>>>(ei);
    k_scan<<<1, 1024>>>();
    k_scatter<<<EB, 256>>>(ei);
    k_prep_pq<<<1, 64>>>(Wemb, bemb, Wcls);

    // step chain: b31 = Y[31] (no kernel); steps k = 30 .. 1
    float* b1 = Y31;
    float* b2 = buf[2];       // zeroed by k_zero
    int idx = 0;
    cudaStreamWaitEvent(0, ev_chunk[0], 0);
    for (int k = KORD - 2; k >= 1; k--) {
        if (k == 23) cudaStreamWaitEvent(0, ev_chunk[1], 0);
        if (k == 15) cudaStreamWaitEvent(0, ev_chunk[2], 0);
        if (k == 7)  cudaStreamWaitEvent(0, ev_chunk[3], 0);
        float* bn = buf[idx];
        k_cheb_step<<<NB, 256>>>(k, bn, b1, b2);
        b2 = b1; b1 = bn; idx = (idx + 1) % 3;
    }
    k_cheb_final_xp<<<NB, 256>>>(b1, b2, bxz, bhz, bxh, bhh, Wgat, asrc, adst);
    k_gat<<<NB, 256>>>(bgat);
    k_out<<<EB, 256>>>(ei, bcls, out);
}